// round 2
// baseline (speedup 1.0000x reference)
#include <cuda_runtime.h>

// InteractionArch: out[b] = concat(dense[b] (128), sparse[b]·dense[b] (26),
//                                  triu_{k=1}(sparse[b]·sparse[b]^T) (325))
// B=16384, F=26, D=128, out stride 479 fp32 (NOT 16B-aligned per row -> scalar stores).

#define B_TOT 16384
#define NF 26
#define DD 128
#define NV 28            // 26 sparse + 1 dense (slot 26) + 1 zero pad (slot 27)
#define OUT_STRIDE 479
#define BPB 2            // batches per block (1 warp each)

__global__ void __launch_bounds__(BPB * 32) interact_kernel(
    const float* __restrict__ dense,
    const float* __restrict__ sparse,
    float* __restrict__ out)
{
    __shared__ float Xs[BPB][NV][DD];

    const int warp = threadIdx.x >> 5;
    const int lane = threadIdx.x & 31;
    const int b    = blockIdx.x * BPB + warp;

    float*        xb  = &Xs[warp][0][0];
    float4*       xb4 = reinterpret_cast<float4*>(xb);
    const float4* sp4 = reinterpret_cast<const float4*>(sparse + (size_t)b * NF * DD);

    // ---- Load phase: coalesced float4 loads, conflict-free row-major smem stores ----
    #pragma unroll
    for (int f = 0; f < NF; f++) {
        xb4[f * 32 + lane] = sp4[f * 32 + lane];
    }
    // dense -> smem slot 26, and pass through to output[0:128] with SCALAR stores
    // (out row base is only 4B-aligned: 479*4 bytes stride).
    float4 dv = reinterpret_cast<const float4*>(dense + (size_t)b * DD)[lane];
    xb4[26 * 32 + lane] = dv;
    {
        float* ob = out + (size_t)b * OUT_STRIDE;
        ob[4 * lane + 0] = dv.x;
        ob[4 * lane + 1] = dv.y;
        ob[4 * lane + 2] = dv.z;
        ob[4 * lane + 3] = dv.w;
    }
    // zero pad slot 27
    xb4[27 * 32 + lane] = make_float4(0.f, 0.f, 0.f, 0.f);

    __syncwarp();

    if (lane >= 28) return;   // 28 upper-tri 4x4 tiles of the 7x7 tile grid

    // ---- Tile mapping: lane -> (ti, tj), ti<=tj, row lengths 7,6,5,4,3,2,1 ----
    int ti = 0, rem = lane;
    while (rem >= 7 - ti) { rem -= 7 - ti; ti++; }
    const int tj = ti + rem;
    const int i0 = 4 * ti;
    const int j0 = 4 * tj;

    const float* __restrict__ pi = xb + i0 * DD;
    const float* __restrict__ pj = xb + j0 * DD;

    float acc[4][4];
    #pragma unroll
    for (int ii = 0; ii < 4; ii++)
        #pragma unroll
        for (int jj = 0; jj < 4; jj++)
            acc[ii][jj] = 0.f;

    // ---- Compute: per-lane k rotation -> conflict-free scalar LDS ----
    #pragma unroll 8
    for (int kk = 0; kk < DD; kk++) {
        const int k = (kk + lane) & (DD - 1);
        float xi[4], xj[4];
        #pragma unroll
        for (int ii = 0; ii < 4; ii++) xi[ii] = pi[ii * DD + k];
        #pragma unroll
        for (int jj = 0; jj < 4; jj++) xj[jj] = pj[jj * DD + k];
        #pragma unroll
        for (int ii = 0; ii < 4; ii++)
            #pragma unroll
            for (int jj = 0; jj < 4; jj++)
                acc[ii][jj] = fmaf(xi[ii], xj[jj], acc[ii][jj]);
    }

    // ---- Epilogue: scatter the needed dots (scalar stores) ----
    float* ob = out + (size_t)b * OUT_STRIDE;
    #pragma unroll
    for (int ii = 0; ii < 4; ii++) {
        #pragma unroll
        for (int jj = 0; jj < 4; jj++) {
            const int i = i0 + ii;
            const int j = j0 + jj;
            if (i < j && j <= 26) {
                int dst;
                if (j == 26) {
                    dst = 128 + i;                                   // sparse·dense
                } else {
                    dst = 154 + i * 25 - (i * (i - 1)) / 2 + (j - i - 1); // pair
                }
                ob[dst] = acc[ii][jj];
            }
        }
    }
}

extern "C" void kernel_launch(void* const* d_in, const int* in_sizes, int n_in,
                              void* d_out, int out_size)
{
    (void)n_in; (void)out_size;
    const float* a = (const float*)d_in[0];
    const float* b = (const float*)d_in[1];
    // dense has B*D = 2,097,152 elems; sparse has B*F*D = 54,525,952 elems.
    const float* dense  = (in_sizes[0] < in_sizes[1]) ? a : b;
    const float* sparse = (in_sizes[0] < in_sizes[1]) ? b : a;

    interact_kernel<<<B_TOT / BPB, BPB * 32>>>(dense, sparse, (float*)d_out);
}